// round 1
// baseline (speedup 1.0000x reference)
#include <cuda_runtime.h>

#define TILE   32
#define HALO   10
#define IN     42          // TILE + HALO
#define IN_PAD 44          // padded row stride for input tiles
#define IMG    512
#define OUTD   502         // IMG - 10 (valid conv output)
#define NPLANE 48          // 16 batches * 3 channels

__global__ void ssim_zero_kernel(float* out, int n) {
    int i = threadIdx.x;
    if (i < n) out[i] = 0.0f;
}

__global__ __launch_bounds__(256) void ssim_kernel(const float* __restrict__ img1,
                                                   const float* __restrict__ img2,
                                                   float* __restrict__ out) {
    __shared__ float sA[IN][IN_PAD];
    __shared__ float sB[IN][IN_PAD];
    __shared__ float h1[IN][TILE];
    __shared__ float h2[IN][TILE];
    __shared__ float h11[IN][TILE];
    __shared__ float h22[IN][TILE];
    __shared__ float h12[IN][TILE];
    __shared__ float wsum[8];

    const int plane = blockIdx.z;            // b*3 + c
    const int batch = plane / 3;
    const int ox0 = blockIdx.x * TILE;
    const int oy0 = blockIdx.y * TILE;

    const float* __restrict__ p1 = img1 + (size_t)plane * IMG * IMG;
    const float* __restrict__ p2 = img2 + (size_t)plane * IMG * IMG;

    const int tx = threadIdx.x;              // 0..31
    const int ty = threadIdx.y;              // 0..7
    const int tid = tx + ty * 32;

    // ---- Load 42x42 halo tile of both images into SMEM (clip to [0,1]) ----
    #pragma unroll
    for (int i = tid; i < IN * IN; i += 256) {
        const int r = i / IN;
        const int c = i - r * IN;
        const int gy = oy0 + r;
        const int gx = ox0 + c;
        float a = 0.0f, b = 0.0f;
        if (gy < IMG && gx < IMG) {
            a = __ldg(p1 + gy * IMG + gx);
            b = __ldg(p2 + gy * IMG + gx);
            a = fminf(fmaxf(a, 0.0f), 1.0f);
            b = fminf(fmaxf(b, 0.0f), 1.0f);
        }
        sA[r][c] = a;
        sB[r][c] = b;
    }
    __syncthreads();

    // ---- Horizontal 11-sums: 42 rows x 32 output cols, 5 moment channels ----
    #pragma unroll
    for (int i = tid; i < IN * TILE; i += 256) {
        const int r = i >> 5;        // / 32
        const int c = i & 31;        // % 32
        float s1 = 0.f, s2 = 0.f, s11 = 0.f, s22 = 0.f, s12 = 0.f;
        #pragma unroll
        for (int k = 0; k < 11; k++) {
            const float a = sA[r][c + k];
            const float b = sB[r][c + k];
            s1  += a;
            s2  += b;
            s11 += a * a;
            s22 += b * b;
            s12 += a * b;
        }
        h1[r][c]  = s1;
        h2[r][c]  = s2;
        h11[r][c] = s11;
        h22[r][c] = s22;
        h12[r][c] = s12;
    }
    __syncthreads();

    // ---- Vertical sliding 11-sum + SSIM. Thread (tx,ty): col tx, rows ty*4..ty*4+3 ----
    const float C1 = 1e-4f;              // 0.01^2
    const float C2 = 9e-4f;              // 0.03^2
    const float inv121 = 1.0f / 121.0f;

    const int r0 = ty * 4;
    float s1 = 0.f, s2 = 0.f, s11 = 0.f, s22 = 0.f, s12 = 0.f;
    #pragma unroll
    for (int k = 0; k < 11; k++) {
        s1  += h1[r0 + k][tx];
        s2  += h2[r0 + k][tx];
        s11 += h11[r0 + k][tx];
        s22 += h22[r0 + k][tx];
        s12 += h12[r0 + k][tx];
    }

    float acc = 0.0f;
    const int ox = ox0 + tx;
    #pragma unroll
    for (int j = 0; j < 4; j++) {
        const int oy = oy0 + r0 + j;
        if (oy < OUTD && ox < OUTD) {
            const float mu1 = s1 * inv121;
            const float mu2 = s2 * inv121;
            const float v1  = s11 * inv121 - mu1 * mu1;
            const float v2  = s22 * inv121 - mu2 * mu2;
            const float v12 = s12 * inv121 - mu1 * mu2;
            const float num = (2.0f * mu1 * mu2 + C1) * (2.0f * v12 + C2);
            const float den = (mu1 * mu1 + mu2 * mu2 + C1) * (v1 + v2 + C2);
            acc += num / den;
        }
        if (j < 3) {
            const int rin  = r0 + j + 11;
            const int rout = r0 + j;
            s1  += h1[rin][tx]  - h1[rout][tx];
            s2  += h2[rin][tx]  - h2[rout][tx];
            s11 += h11[rin][tx] - h11[rout][tx];
            s22 += h22[rin][tx] - h22[rout][tx];
            s12 += h12[rin][tx] - h12[rout][tx];
        }
    }

    // ---- Block reduction ----
    #pragma unroll
    for (int o = 16; o > 0; o >>= 1)
        acc += __shfl_down_sync(0xffffffffu, acc, o);
    if (tx == 0) wsum[ty] = acc;
    __syncthreads();
    if (tid == 0) {
        float t = 0.0f;
        #pragma unroll
        for (int i = 0; i < 8; i++) t += wsum[i];
        const float scale = 1.0f / (3.0f * (float)OUTD * (float)OUTD);
        atomicAdd(out + batch, t * scale);
    }
}

extern "C" void kernel_launch(void* const* d_in, const int* in_sizes, int n_in,
                              void* d_out, int out_size) {
    const float* img1 = (const float*)d_in[0];
    const float* img2 = (const float*)d_in[1];
    float* out = (float*)d_out;

    ssim_zero_kernel<<<1, 32>>>(out, out_size);

    dim3 block(32, 8);
    dim3 grid((OUTD + TILE - 1) / TILE, (OUTD + TILE - 1) / TILE, NPLANE);
    ssim_kernel<<<grid, block>>>(img1, img2, out);
}

// round 3
// speedup vs baseline: 1.0652x; 1.0652x over previous
#include <cuda_runtime.h>

#define TILE   32
#define IN     42          // TILE + 10 halo
#define IN_PAD 43          // odd pad: conflict-free strided row access
#define H_PAD  33          // odd pad for h-sum buffers
#define IMG    512
#define OUTD   502
#define NPLANE 48

__global__ void ssim_zero_kernel(float* out, int n) {
    int i = threadIdx.x;
    if (i < n) out[i] = 0.0f;
}

__global__ __launch_bounds__(256) void ssim_kernel(const float* __restrict__ img1,
                                                   const float* __restrict__ img2,
                                                   float* __restrict__ out) {
    __shared__ float sA[IN][IN_PAD];
    __shared__ float sB[IN][IN_PAD];
    __shared__ float hA[IN][H_PAD];   // sum a
    __shared__ float hB[IN][H_PAD];   // sum b
    __shared__ float hP[IN][H_PAD];   // sum (a+b)^2
    __shared__ float hM[IN][H_PAD];   // sum (a-b)^2
    __shared__ float wsum[8];

    const int plane = blockIdx.z;
    const int batch = plane / 3;
    const int ox0 = blockIdx.x * TILE;
    const int oy0 = blockIdx.y * TILE;

    const float* __restrict__ p1 = img1 + (size_t)plane * IMG * IMG;
    const float* __restrict__ p2 = img2 + (size_t)plane * IMG * IMG;

    const int tid = threadIdx.x + threadIdx.y * 32;

    // ---- Load 42x42 halo tile (clip to [0,1]); zeros outside image ----
    #pragma unroll
    for (int i = tid; i < IN * IN; i += 256) {
        const int r = i / IN;
        const int c = i - r * IN;
        const int gy = oy0 + r;
        const int gx = ox0 + c;
        float a = 0.0f, b = 0.0f;
        if (gy < IMG && gx < IMG) {
            a = __ldg(p1 + gy * IMG + gx);
            b = __ldg(p2 + gy * IMG + gx);
            a = __saturatef(a);
            b = __saturatef(b);
        }
        sA[r][c] = a;
        sB[r][c] = b;
    }
    __syncthreads();

    // ---- Pass 1: horizontal sliding 11-sums. 84 threads: 2 per row x 42 rows,
    //      each slides over 16 consecutive output columns. ----
    if (tid < 84) {
        const int row = tid >> 1;
        const int c0  = (tid & 1) * 16;
        float sa = 0.f, sb = 0.f, sp = 0.f, sm = 0.f;
        #pragma unroll
        for (int k = 0; k < 10; k++) {          // first 10 taps of window
            const float a = sA[row][c0 + k];
            const float b = sB[row][c0 + k];
            const float p = a + b, m = a - b;
            sa += a; sb += b; sp += p * p; sm += m * m;
        }
        #pragma unroll
        for (int j = 0; j < 16; j++) {
            {   // enter col c0+j+10
                const float a = sA[row][c0 + j + 10];
                const float b = sB[row][c0 + j + 10];
                const float p = a + b, m = a - b;
                sa += a; sb += b; sp += p * p; sm += m * m;
            }
            hA[row][c0 + j] = sa;
            hB[row][c0 + j] = sb;
            hP[row][c0 + j] = sp;
            hM[row][c0 + j] = sm;
            {   // exit col c0+j (for next window)
                const float a = sA[row][c0 + j];
                const float b = sB[row][c0 + j];
                const float p = a + b, m = a - b;
                sa -= a; sb -= b; sp -= p * p; sm -= m * m;
            }
        }
    }
    __syncthreads();

    // ---- Pass 2: vertical sliding 11-sums + SSIM. 128 threads:
    //      col = tid&31, row-chunk of 8 = tid>>5. ----
    const float C1 = 1e-4f;
    const float C2 = 9e-4f;
    const float inv121  = 1.0f / 121.0f;
    const float inv242  = 1.0f / 242.0f;
    const float inv484  = 1.0f / 484.0f;

    float acc = 0.0f;
    if (tid < 128) {
        const int col = tid & 31;
        const int r0  = (tid >> 5) * 8;
        const int ox  = ox0 + col;

        float sa = 0.f, sb = 0.f, sp = 0.f, sm = 0.f;
        #pragma unroll
        for (int k = 0; k < 10; k++) {
            sa += hA[r0 + k][col];
            sb += hB[r0 + k][col];
            sp += hP[r0 + k][col];
            sm += hM[r0 + k][col];
        }
        #pragma unroll
        for (int j = 0; j < 8; j++) {
            sa += hA[r0 + j + 10][col];
            sb += hB[r0 + j + 10][col];
            sp += hP[r0 + j + 10][col];
            sm += hM[r0 + j + 10][col];

            const int oy = oy0 + r0 + j;
            if (oy < OUTD && ox < OUTD) {
                const float mu1 = sa * inv121;
                const float mu2 = sb * inv121;
                const float musq = mu1 * mu1 + mu2 * mu2;
                const float mu12 = mu1 * mu2;
                const float e_sq = sp * inv242 + sm * inv242;   // E[a^2 + b^2]
                const float e_ab = sp * inv484 - sm * inv484;   // E[ab]
                const float vsum = e_sq - musq;                 // v1 + v2
                const float v12  = e_ab - mu12;
                const float num = (2.0f * mu12 + C1) * (2.0f * v12 + C2);
                const float den = (musq + C1) * (vsum + C2);
                acc += num / den;
            }
            sa -= hA[r0 + j][col];
            sb -= hB[r0 + j][col];
            sp -= hP[r0 + j][col];
            sm -= hM[r0 + j][col];
        }
    }

    // ---- Block reduction ----
    #pragma unroll
    for (int o = 16; o > 0; o >>= 1)
        acc += __shfl_down_sync(0xffffffffu, acc, o);
    if ((tid & 31) == 0) wsum[tid >> 5] = acc;
    __syncthreads();
    if (tid == 0) {
        float t = 0.0f;
        #pragma unroll
        for (int i = 0; i < 8; i++) t += wsum[i];
        const float scale = 1.0f / (3.0f * (float)OUTD * (float)OUTD);
        atomicAdd(out + batch, t * scale);
    }
}

extern "C" void kernel_launch(void* const* d_in, const int* in_sizes, int n_in,
                              void* d_out, int out_size) {
    const float* img1 = (const float*)d_in[0];
    const float* img2 = (const float*)d_in[1];
    float* out = (float*)d_out;

    ssim_zero_kernel<<<1, 32>>>(out, out_size);

    dim3 block(32, 8);
    dim3 grid((OUTD + TILE - 1) / TILE, (OUTD + TILE - 1) / TILE, NPLANE);
    ssim_kernel<<<grid, block>>>(img1, img2, out);
}

// round 5
// speedup vs baseline: 1.7208x; 1.6154x over previous
#include <cuda_runtime.h>

#define TILE_W   32          // output cols per block
#define TILE_H   54          // output rows per block
#define IN_R     64          // input rows  = TILE_H + 10
#define IN_C     42          // input cols  = TILE_W + 10
#define IN_PAD   43          // odd pad -> conflict-free strided LDS.32
#define H_PAD    33          // float4 row stride for H buffer
#define IMG      512
#define OUTD     502
#define NPLANE   48

// dynamic smem layout (bytes)
#define H_BYTES   (IN_R * H_PAD * 16)            // 33792
#define SA_BYTES  (IN_R * IN_PAD * 4)            // 11008
#define SMEM_TOTAL (H_BYTES + 2 * SA_BYTES + 32) // 55840

__global__ void ssim_zero_kernel(float* out, int n) {
    int i = threadIdx.x;
    if (i < n) out[i] = 0.0f;
}

__global__ __launch_bounds__(256) void ssim_kernel(const float* __restrict__ img1,
                                                   const float* __restrict__ img2,
                                                   float* __restrict__ out) {
    extern __shared__ char smem_raw[];
    float4 (*H)[H_PAD]  = (float4 (*)[H_PAD])(smem_raw);                       // 16B aligned
    float  (*sA)[IN_PAD] = (float (*)[IN_PAD])(smem_raw + H_BYTES);
    float  (*sB)[IN_PAD] = (float (*)[IN_PAD])(smem_raw + H_BYTES + SA_BYTES);
    float* wsum = (float*)(smem_raw + H_BYTES + 2 * SA_BYTES);

    const int plane = blockIdx.z;
    const int batch = plane / 3;
    const int ox0 = blockIdx.x * TILE_W;
    const int oy0 = blockIdx.y * TILE_H;

    const float* __restrict__ p1 = img1 + (size_t)plane * IMG * IMG;
    const float* __restrict__ p2 = img2 + (size_t)plane * IMG * IMG;

    const int tid = threadIdx.x;

    // ---- Phase 0: load 64x42 halo tile of both images, clipped; zeros outside ----
    #pragma unroll
    for (int i = tid; i < IN_R * IN_C; i += 256) {
        const int r = i / IN_C;
        const int c = i - r * IN_C;
        const int gy = oy0 + r;
        const int gx = ox0 + c;
        float a = 0.0f, b = 0.0f;
        if (gy < IMG && gx < IMG) {
            a = __saturatef(__ldg(p1 + gy * IMG + gx));
            b = __saturatef(__ldg(p2 + gy * IMG + gx));
        }
        sA[r][c] = a;
        sB[r][c] = b;
    }
    __syncthreads();

    // ---- Phase 1: horizontal sliding 11-sums. All 256 threads:
    //      row = tid&63 (0..63), span = tid>>6 (0..3), 8 output cols per span. ----
    {
        const int row = tid & 63;
        const int c0  = (tid >> 6) * 8;
        float sa = 0.f, sb = 0.f, sp = 0.f, sm = 0.f;
        #pragma unroll
        for (int k = 0; k < 10; k++) {
            const float a = sA[row][c0 + k];
            const float b = sB[row][c0 + k];
            const float p = a + b, m = a - b;
            sa += a; sb += b; sp += p * p; sm += m * m;
        }
        #pragma unroll
        for (int j = 0; j < 8; j++) {
            {   // enter
                const float a = sA[row][c0 + j + 10];
                const float b = sB[row][c0 + j + 10];
                const float p = a + b, m = a - b;
                sa += a; sb += b; sp += p * p; sm += m * m;
            }
            H[row][c0 + j] = make_float4(sa, sb, sp, sm);
            {   // exit
                const float a = sA[row][c0 + j];
                const float b = sB[row][c0 + j];
                const float p = a + b, m = a - b;
                sa -= a; sb -= b; sp -= p * p; sm -= m * m;
            }
        }
    }
    __syncthreads();

    // ---- Phase 2: vertical sliding 11-sums + SSIM. All 256 threads:
    //      col = tid&31, q = tid>>5 (0..7), rows 7q..7q+6 (tile rows < 54). ----
    const float C1 = 1e-4f;
    const float C2 = 9e-4f;
    const float inv121 = 1.0f / 121.0f;
    const float inv242 = 1.0f / 242.0f;
    const float inv484 = 1.0f / 484.0f;

    float acc = 0.0f;
    {
        const int col = tid & 31;
        const int r0  = (tid >> 5) * 7;
        const int ox  = ox0 + col;

        float sa = 0.f, sb = 0.f, sp = 0.f, sm = 0.f;
        #pragma unroll
        for (int k = 0; k < 10; k++) {
            const float4 h = H[r0 + k][col];
            sa += h.x; sb += h.y; sp += h.z; sm += h.w;
        }
        #pragma unroll
        for (int j = 0; j < 7; j++) {
            if (r0 + j < TILE_H) {                 // tile-local guard (q=7 tail)
                {
                    const float4 h = H[r0 + j + 10][col];
                    sa += h.x; sb += h.y; sp += h.z; sm += h.w;
                }
                const int oy = oy0 + r0 + j;
                if (oy < OUTD && ox < OUTD) {
                    const float mu1  = sa * inv121;
                    const float mu2  = sb * inv121;
                    const float musq = mu1 * mu1 + mu2 * mu2;
                    const float mu12 = mu1 * mu2;
                    const float e_sq = (sp + sm) * inv242;   // E[a^2 + b^2]
                    const float e_ab = (sp - sm) * inv484;   // E[ab]
                    const float vsum = e_sq - musq;          // v1 + v2
                    const float v12  = e_ab - mu12;
                    const float num = (2.0f * mu12 + C1) * (2.0f * v12 + C2);
                    const float den = (musq + C1) * (vsum + C2);
                    acc += num / den;
                }
                {
                    const float4 h = H[r0 + j][col];
                    sa -= h.x; sb -= h.y; sp -= h.z; sm -= h.w;
                }
            }
        }
    }

    // ---- Block reduction ----
    #pragma unroll
    for (int o = 16; o > 0; o >>= 1)
        acc += __shfl_down_sync(0xffffffffu, acc, o);
    if ((tid & 31) == 0) wsum[tid >> 5] = acc;
    __syncthreads();
    if (tid == 0) {
        float t = 0.0f;
        #pragma unroll
        for (int i = 0; i < 8; i++) t += wsum[i];
        const float scale = 1.0f / (3.0f * (float)OUTD * (float)OUTD);
        atomicAdd(out + batch, t * scale);
    }
}

extern "C" void kernel_launch(void* const* d_in, const int* in_sizes, int n_in,
                              void* d_out, int out_size) {
    const float* img1 = (const float*)d_in[0];
    const float* img2 = (const float*)d_in[1];
    float* out = (float*)d_out;

    cudaFuncSetAttribute(ssim_kernel,
                         cudaFuncAttributeMaxDynamicSharedMemorySize, SMEM_TOTAL);

    ssim_zero_kernel<<<1, 32>>>(out, out_size);

    dim3 block(256);
    dim3 grid((OUTD + TILE_W - 1) / TILE_W,   // 16
              (OUTD + TILE_H - 1) / TILE_H,   // 10
              NPLANE);                        // 48
    ssim_kernel<<<grid, block, SMEM_TOTAL>>>(img1, img2, out);
}

// round 6
// speedup vs baseline: 1.9183x; 1.1148x over previous
#include <cuda_runtime.h>

#define TILE_W   32          // output cols per block
#define TILE_H   42          // output rows per block
#define IN_R     52          // input rows  = TILE_H + 10
#define IN_C     42          // input cols  = TILE_W + 10
#define AB_PAD   43          // float2 row stride (odd -> conflict-free column access)
#define H_PAD    33          // float4 row stride (odd -> conflict-free column access)
#define IMG      512
#define OUTD     502
#define NPLANE   48

// dynamic smem layout (bytes)
#define H_BYTES    (IN_R * H_PAD * 16)              // 27456
#define AB_BYTES   (IN_R * AB_PAD * 8)              // 17888
#define SMEM_TOTAL (H_BYTES + AB_BYTES + 64)        // 45408  -> 5 CTAs/SM

__global__ void ssim_zero_kernel(float* out, int n) {
    int i = threadIdx.x;
    if (i < n) out[i] = 0.0f;
}

__global__ __launch_bounds__(256, 5) void ssim_kernel(const float* __restrict__ img1,
                                                      const float* __restrict__ img2,
                                                      float* __restrict__ out) {
    extern __shared__ char smem_raw[];
    float4 (*H)[H_PAD]   = (float4 (*)[H_PAD])(smem_raw);
    float2 (*AB)[AB_PAD] = (float2 (*)[AB_PAD])(smem_raw + H_BYTES);
    float* wsum = (float*)(smem_raw + H_BYTES + AB_BYTES);

    const int plane = blockIdx.z;
    const int batch = plane / 3;
    const int ox0 = blockIdx.x * TILE_W;
    const int oy0 = blockIdx.y * TILE_H;

    const float2* __restrict__ p1 = (const float2*)(img1 + (size_t)plane * IMG * IMG);
    const float2* __restrict__ p2 = (const float2*)(img2 + (size_t)plane * IMG * IMG);
    const int row2 = IMG / 2;            // float2 per image row
    const int cx0  = ox0 >> 1;           // float2 col of tile origin (ox0 even)

    const int tid = threadIdx.x;

    // ---- Phase 0: load 52 x 21-float2 halo tile of both images, clipped.
    //      AB[r][c] = (a, b) interleaved. ----
    #pragma unroll
    for (int i = tid; i < IN_R * 21; i += 256) {
        const int r  = i / 21;
        const int c2 = i - r * 21;
        const int gy = oy0 + r;
        const int gx = ox0 + 2 * c2;
        float2 a = make_float2(0.f, 0.f), b = a;
        if (gy < IMG && gx < IMG) {
            a = __ldg(p1 + gy * row2 + cx0 + c2);
            b = __ldg(p2 + gy * row2 + cx0 + c2);
            a.x = __saturatef(a.x); a.y = __saturatef(a.y);
            b.x = __saturatef(b.x); b.y = __saturatef(b.y);
        }
        AB[r][2 * c2]     = make_float2(a.x, b.x);
        AB[r][2 * c2 + 1] = make_float2(a.y, b.y);
    }
    __syncthreads();

    // ---- Phase 1: horizontal sliding 11-sums. 208 threads:
    //      row = tid % 52, span = tid / 52 (8 output cols each). ----
    if (tid < 4 * IN_R) {
        const int row = tid % IN_R;
        const int c0  = (tid / IN_R) * 8;
        float sa = 0.f, sb = 0.f, sp = 0.f, sm = 0.f;
        #pragma unroll
        for (int k = 0; k < 10; k++) {
            const float2 ab = AB[row][c0 + k];
            const float p = ab.x + ab.y, m = ab.x - ab.y;
            sa += ab.x; sb += ab.y; sp += p * p; sm += m * m;
        }
        #pragma unroll
        for (int j = 0; j < 8; j++) {
            {   // enter
                const float2 ab = AB[row][c0 + j + 10];
                const float p = ab.x + ab.y, m = ab.x - ab.y;
                sa += ab.x; sb += ab.y; sp += p * p; sm += m * m;
            }
            H[row][c0 + j] = make_float4(sa, sb, sp, sm);
            {   // exit
                const float2 ab = AB[row][c0 + j];
                const float p = ab.x + ab.y, m = ab.x - ab.y;
                sa -= ab.x; sb -= ab.y; sp -= p * p; sm -= m * m;
            }
        }
    }
    __syncthreads();

    // ---- Phase 2: vertical sliding 11-sums + SSIM. 224 threads:
    //      col = tid & 31, group = tid >> 5 (0..6), rows group*6 .. group*6+5. ----
    const float C1 = 1e-4f;
    const float C2 = 9e-4f;
    const float inv121 = 1.0f / 121.0f;
    const float inv242 = 1.0f / 242.0f;
    const float inv484 = 1.0f / 484.0f;

    float acc = 0.0f;
    if (tid < 224) {
        const int col = tid & 31;
        const int r0  = (tid >> 5) * 6;
        const bool oxok = (ox0 + col) < OUTD;

        float sa = 0.f, sb = 0.f, sp = 0.f, sm = 0.f;
        #pragma unroll
        for (int k = 0; k < 10; k++) {
            const float4 h = H[r0 + k][col];
            sa += h.x; sb += h.y; sp += h.z; sm += h.w;
        }
        #pragma unroll
        for (int j = 0; j < 6; j++) {
            {
                const float4 h = H[r0 + j + 10][col];
                sa += h.x; sb += h.y; sp += h.z; sm += h.w;
            }
            const int oy = oy0 + r0 + j;
            if (oxok && oy < OUTD) {
                const float mu1  = sa * inv121;
                const float mu2  = sb * inv121;
                const float musq = mu1 * mu1 + mu2 * mu2;
                const float mu12 = mu1 * mu2;
                const float e_sq = (sp + sm) * inv242;   // E[a^2 + b^2]
                const float e_ab = (sp - sm) * inv484;   // E[ab]
                const float vsum = e_sq - musq;          // v1 + v2
                const float v12  = e_ab - mu12;
                const float num = (2.0f * mu12 + C1) * (2.0f * v12 + C2);
                const float den = (musq + C1) * (vsum + C2);
                acc += __fdividef(num, den);
            }
            {
                const float4 h = H[r0 + j][col];
                sa -= h.x; sb -= h.y; sp -= h.z; sm -= h.w;
            }
        }
    }

    // ---- Block reduction ----
    #pragma unroll
    for (int o = 16; o > 0; o >>= 1)
        acc += __shfl_down_sync(0xffffffffu, acc, o);
    if ((tid & 31) == 0) wsum[tid >> 5] = acc;
    __syncthreads();
    if (tid == 0) {
        float t = 0.0f;
        #pragma unroll
        for (int i = 0; i < 8; i++) t += wsum[i];
        const float scale = 1.0f / (3.0f * (float)OUTD * (float)OUTD);
        atomicAdd(out + batch, t * scale);
    }
}

extern "C" void kernel_launch(void* const* d_in, const int* in_sizes, int n_in,
                              void* d_out, int out_size) {
    const float* img1 = (const float*)d_in[0];
    const float* img2 = (const float*)d_in[1];
    float* out = (float*)d_out;

    cudaFuncSetAttribute(ssim_kernel,
                         cudaFuncAttributeMaxDynamicSharedMemorySize, SMEM_TOTAL);

    ssim_zero_kernel<<<1, 32>>>(out, out_size);

    dim3 block(256);
    dim3 grid((OUTD + TILE_W - 1) / TILE_W,   // 16
              (OUTD + TILE_H - 1) / TILE_H,   // 12
              NPLANE);                        // 48
    ssim_kernel<<<grid, block, SMEM_TOTAL>>>(img1, img2, out);
}

// round 9
// speedup vs baseline: 1.9470x; 1.0150x over previous
#include <cuda_runtime.h>

#define TILE_W   32          // output cols per block
#define TILE_H   42          // output rows per block
#define IN_R     52          // input rows  = TILE_H + 10
#define IN_C     42          // input cols  = TILE_W + 10
#define AB_PAD   43          // float2 row stride (odd -> conflict-free column access)
#define H_PAD    33          // float4 row stride (odd -> conflict-free column access)
#define IMG      512
#define OUTD     502
#define NPLANE   48

// dynamic smem layout (bytes)
#define H_BYTES    (IN_R * H_PAD * 16)              // 27456
#define AB_BYTES   (IN_R * AB_PAD * 8)              // 17888
#define SMEM_TOTAL (H_BYTES + AB_BYTES + 64)        // 45408  -> 5 CTAs/SM

__global__ void ssim_zero_kernel(float* out, int n) {
    int i = threadIdx.x;
    if (i < n) out[i] = 0.0f;
}

__global__ __launch_bounds__(256, 5) void ssim_kernel(const float* __restrict__ img1,
                                                      const float* __restrict__ img2,
                                                      float* __restrict__ out) {
    extern __shared__ char smem_raw[];
    float4 (*H)[H_PAD]   = (float4 (*)[H_PAD])(smem_raw);
    float2 (*AB)[AB_PAD] = (float2 (*)[AB_PAD])(smem_raw + H_BYTES);
    float* wsum = (float*)(smem_raw + H_BYTES + AB_BYTES);

    const int plane = blockIdx.z;
    const int batch = plane / 3;
    const int ox0 = blockIdx.x * TILE_W;
    const int oy0 = blockIdx.y * TILE_H;

    const float2* __restrict__ p1 = (const float2*)(img1 + (size_t)plane * IMG * IMG);
    const float2* __restrict__ p2 = (const float2*)(img2 + (size_t)plane * IMG * IMG);
    const int row2 = IMG / 2;            // float2 per image row
    const int cx0  = ox0 >> 1;           // float2 col of tile origin (ox0 even)

    const int tid = threadIdx.x;

    // ---- Phase 0: load 52 x 21-float2 halo tile of both images, clipped.
    //      AB[r][c] = (a, b) interleaved. ----
    #pragma unroll
    for (int i = tid; i < IN_R * 21; i += 256) {
        const int r  = i / 21;
        const int c2 = i - r * 21;
        const int gy = oy0 + r;
        const int gx = ox0 + 2 * c2;
        float2 a = make_float2(0.f, 0.f), b = a;
        if (gy < IMG && gx < IMG) {
            a = __ldg(p1 + gy * row2 + cx0 + c2);
            b = __ldg(p2 + gy * row2 + cx0 + c2);
            a.x = __saturatef(a.x); a.y = __saturatef(a.y);
            b.x = __saturatef(b.x); b.y = __saturatef(b.y);
        }
        AB[r][2 * c2]     = make_float2(a.x, b.x);
        AB[r][2 * c2 + 1] = make_float2(a.y, b.y);
    }
    __syncthreads();

    // ---- Phase 1: horizontal sliding 11-sums. 208 threads:
    //      row = tid % 52, span = tid / 52 (8 output cols each).
    //      Exit taps (cols c0..c0+7) are the first 8 prologue loads -> kept in
    //      registers; no exit LDS. ----
    if (tid < 4 * IN_R) {
        const int row = tid % IN_R;
        const int c0  = (tid / IN_R) * 8;
        float2 ring[8];                  // prologue taps 0..7 (the future exits)
        float sa = 0.f, sb = 0.f, sp = 0.f, sm = 0.f;
        #pragma unroll
        for (int k = 0; k < 10; k++) {
            const float2 ab = AB[row][c0 + k];
            if (k < 8) ring[k] = ab;
            const float p = ab.x + ab.y, m = ab.x - ab.y;
            sa += ab.x; sb += ab.y; sp += p * p; sm += m * m;
        }
        #pragma unroll
        for (int j = 0; j < 8; j++) {
            {   // enter col c0+j+10
                const float2 ab = AB[row][c0 + j + 10];
                const float p = ab.x + ab.y, m = ab.x - ab.y;
                sa += ab.x; sb += ab.y; sp += p * p; sm += m * m;
            }
            H[row][c0 + j] = make_float4(sa, sb, sp, sm);
            {   // exit col c0+j from registers
                const float2 ab = ring[j];
                const float p = ab.x + ab.y, m = ab.x - ab.y;
                sa -= ab.x; sb -= ab.y; sp -= p * p; sm -= m * m;
            }
        }
    }
    __syncthreads();

    // ---- Phase 2: vertical sliding 11-sums + SSIM. 224 threads:
    //      col = tid & 31, group = tid >> 5 (0..6), rows group*6 .. group*6+5.
    //      Exit taps (rows r0..r0+5) kept in registers. ----
    const float C1 = 1e-4f;
    const float C2 = 9e-4f;
    const float inv121 = 1.0f / 121.0f;
    const float inv242 = 1.0f / 242.0f;
    const float inv484 = 1.0f / 484.0f;

    float acc = 0.0f;
    if (tid < 224) {
        const int col = tid & 31;
        const int r0  = (tid >> 5) * 6;
        const bool oxok = (ox0 + col) < OUTD;

        float4 ringv[6];                 // prologue taps rows r0..r0+5
        float sa = 0.f, sb = 0.f, sp = 0.f, sm = 0.f;
        #pragma unroll
        for (int k = 0; k < 10; k++) {
            const float4 h = H[r0 + k][col];
            if (k < 6) ringv[k] = h;
            sa += h.x; sb += h.y; sp += h.z; sm += h.w;
        }
        #pragma unroll
        for (int j = 0; j < 6; j++) {
            {
                const float4 h = H[r0 + j + 10][col];
                sa += h.x; sb += h.y; sp += h.z; sm += h.w;
            }
            const int oy = oy0 + r0 + j;
            if (oxok && oy < OUTD) {
                const float mu1  = sa * inv121;
                const float mu2  = sb * inv121;
                const float musq = mu1 * mu1 + mu2 * mu2;
                const float mu12 = mu1 * mu2;
                const float e_sq = (sp + sm) * inv242;   // E[a^2 + b^2]
                const float e_ab = (sp - sm) * inv484;   // E[ab]
                const float vsum = e_sq - musq;          // v1 + v2
                const float v12  = e_ab - mu12;
                const float num = (2.0f * mu12 + C1) * (2.0f * v12 + C2);
                const float den = (musq + C1) * (vsum + C2);
                acc += __fdividef(num, den);
            }
            {   // exit row r0+j from registers
                const float4 h = ringv[j];
                sa -= h.x; sb -= h.y; sp -= h.z; sm -= h.w;
            }
        }
    }

    // ---- Block reduction ----
    #pragma unroll
    for (int o = 16; o > 0; o >>= 1)
        acc += __shfl_down_sync(0xffffffffu, acc, o);
    if ((tid & 31) == 0) wsum[tid >> 5] = acc;
    __syncthreads();
    if (tid == 0) {
        float t = 0.0f;
        #pragma unroll
        for (int i = 0; i < 8; i++) t += wsum[i];
        const float scale = 1.0f / (3.0f * (float)OUTD * (float)OUTD);
        atomicAdd(out + batch, t * scale);
    }
}

extern "C" void kernel_launch(void* const* d_in, const int* in_sizes, int n_in,
                              void* d_out, int out_size) {
    const float* img1 = (const float*)d_in[0];
    const float* img2 = (const float*)d_in[1];
    float* out = (float*)d_out;

    cudaFuncSetAttribute(ssim_kernel,
                         cudaFuncAttributeMaxDynamicSharedMemorySize, SMEM_TOTAL);

    ssim_zero_kernel<<<1, 32>>>(out, out_size);

    dim3 block(256);
    dim3 grid((OUTD + TILE_W - 1) / TILE_W,   // 16
              (OUTD + TILE_H - 1) / TILE_H,   // 12
              NPLANE);                        // 48
    ssim_kernel<<<grid, block, SMEM_TOTAL>>>(img1, img2, out);
}